// round 1
// baseline (speedup 1.0000x reference)
#include <cuda_runtime.h>
#include <cuda_bf16.h>

// Problem: custom_loss_57956288692862
// x: [16384, 1024] fp32  -> groups of 4 rows: q = 4b+0, a = 4b+1, (dead = 4b+2), c = 4b+3
// target: [2, 4096] int32
// out (fp32, 4097 elems assumed): out[0] = mean loss, out[1+b] = (correct_b == target[0][b])
//
// Per group b:
//   qa = dot(q,a)/(|q||a|); ac = dot(a,c)/(|a||c|); qc = dot(q,c)/(|q||c|)
//   up   = max((1-t0)*e^qa + (1-t1)*e^qc, 1e-8)
//   down = max(t0*e^qa + t1*e^qc, 1e-8)
//   loss_b = log(up + e^ac) - log(down)
//   eq_b = ((qa > qc) == t0)

#define NB 4096        // number of groups
#define D  1024        // feature dim
#define THREADS 256    // one float4 per row per thread (256*4 = 1024)

__global__ void zero_out0_kernel(float* out) {
    if (threadIdx.x == 0) out[0] = 0.0f;
}

__global__ __launch_bounds__(THREADS)
void loss_kernel(const float* __restrict__ x,
                 const int* __restrict__ target,
                 float* __restrict__ out,
                 int out_size) {
    const int b = blockIdx.x;
    const int t = threadIdx.x;

    // Group base: 4 rows * 1024 floats = 4096 floats = 1024 float4
    const float4* __restrict__ g =
        reinterpret_cast<const float4*>(x + (size_t)b * (4 * D));

    // Three independent vector loads (MLP=3) — row stride = 256 float4
    float4 q4 = g[t];            // row 4b+0
    float4 a4 = g[256 + t];      // row 4b+1
    float4 c4 = g[768 + t];      // row 4b+3

    // 6 partial sums
    float nq = q4.x * q4.x + q4.y * q4.y + q4.z * q4.z + q4.w * q4.w;
    float na = a4.x * a4.x + a4.y * a4.y + a4.z * a4.z + a4.w * a4.w;
    float nc = c4.x * c4.x + c4.y * c4.y + c4.z * c4.z + c4.w * c4.w;
    float qa = q4.x * a4.x + q4.y * a4.y + q4.z * a4.z + q4.w * a4.w;
    float ac = a4.x * c4.x + a4.y * c4.y + a4.z * c4.z + a4.w * c4.w;
    float qc = q4.x * c4.x + q4.y * c4.y + q4.z * c4.z + q4.w * c4.w;

    // Warp reduction (full 32-lane butterfly on all 6 quantities)
    #pragma unroll
    for (int off = 16; off > 0; off >>= 1) {
        nq += __shfl_xor_sync(0xFFFFFFFFu, nq, off);
        na += __shfl_xor_sync(0xFFFFFFFFu, na, off);
        nc += __shfl_xor_sync(0xFFFFFFFFu, nc, off);
        qa += __shfl_xor_sync(0xFFFFFFFFu, qa, off);
        ac += __shfl_xor_sync(0xFFFFFFFFu, ac, off);
        qc += __shfl_xor_sync(0xFFFFFFFFu, qc, off);
    }

    __shared__ float s[6][8];   // 8 warps
    const int wid = t >> 5;
    const int lid = t & 31;
    if (lid == 0) {
        s[0][wid] = nq; s[1][wid] = na; s[2][wid] = nc;
        s[3][wid] = qa; s[4][wid] = ac; s[5][wid] = qc;
    }
    __syncthreads();

    if (t == 0) {
        float snq = 0.f, sna = 0.f, snc = 0.f, sqa = 0.f, sac = 0.f, sqc = 0.f;
        #pragma unroll
        for (int w = 0; w < 8; w++) {
            snq += s[0][w]; sna += s[1][w]; snc += s[2][w];
            sqa += s[3][w]; sac += s[4][w]; sqc += s[5][w];
        }

        // normalize: v / max(|v|, 1e-12). Norms of 1024-dim gaussians ~32; no clamp risk,
        // but keep it exact:
        float iq = 1.0f / fmaxf(sqrtf(snq), 1e-12f);
        float ia = 1.0f / fmaxf(sqrtf(sna), 1e-12f);
        float ic = 1.0f / fmaxf(sqrtf(snc), 1e-12f);

        float dqa = sqa * iq * ia;   // temperature = 1.0
        float dac = sac * ia * ic;
        float dqc = sqc * iq * ic;

        float t0 = (float)target[b];        // target[0][b]
        float t1 = (float)target[NB + b];   // target[1][b]

        float eqa = expf(dqa);
        float eac = expf(dac);
        float eqc = expf(dqc);

        float up   = fmaxf((1.0f - t0) * eqa + (1.0f - t1) * eqc, 1e-8f);
        float down = fmaxf(t0 * eqa + t1 * eqc, 1e-8f);

        float loss = logf(up + eac) - logf(down);
        atomicAdd(&out[0], loss * (1.0f / (float)NB));

        int correct = (dqa > dqc) ? 1 : 0;
        float eq = (correct == (int)t0) ? 1.0f : 0.0f;
        if (1 + b < out_size) out[1 + b] = eq;
    }
}

extern "C" void kernel_launch(void* const* d_in, const int* in_sizes, int n_in,
                              void* d_out, int out_size) {
    const float* x      = (const float*)d_in[0];
    const int*   target = (const int*)d_in[1];
    float*       out    = (float*)d_out;

    zero_out0_kernel<<<1, 32>>>(out);
    loss_kernel<<<NB, THREADS>>>(x, target, out, out_size);
}

// round 2
// speedup vs baseline: 1.3894x; 1.3894x over previous
#include <cuda_runtime.h>
#include <cuda_bf16.h>

// custom_loss_57956288692862
// x: [16384,1024] fp32 -> 4096 groups of 4 rows: q=4b+0, a=4b+1, dead=4b+2, c=4b+3
// target: [2,4096] int32
// out fp32[4097]: out[0]=mean loss, out[1+b]=eq flag
//
// One WARP per group. 2 groups per warp, grid=256 CTAs x 8 warps -> single wave
// at 2 CTAs/SM. No block-wide sync in hot path; per-CTA loss aggregation -> 1 atomic.

#define NB 4096
#define D  1024
#define THREADS 256
#define GRID 256
#define WARPS_TOTAL (GRID * 8)          // 2048
#define GROUPS_PER_WARP 2               // 2048 * 2 = 4096

__global__ void zero_out0_kernel(float* out) {
    if (threadIdx.x == 0) out[0] = 0.0f;
}

__device__ __forceinline__ float warp_sum(float v) {
    #pragma unroll
    for (int off = 16; off > 0; off >>= 1)
        v += __shfl_xor_sync(0xFFFFFFFFu, v, off);
    return v;
}

__global__ __launch_bounds__(THREADS, 2)
void loss_kernel(const float* __restrict__ x,
                 const int* __restrict__ target,
                 float* __restrict__ out,
                 int out_size) {
    const int t   = threadIdx.x;
    const int wid = t >> 5;
    const int lid = t & 31;
    const int warpGlobal = blockIdx.x * 8 + wid;

    float locLoss = 0.0f;   // lane 0 accumulates across its groups

    #pragma unroll
    for (int gi = 0; gi < GROUPS_PER_WARP; gi++) {
        const int b = warpGlobal + gi * WARPS_TOTAL;

        // Group base: 4 rows * 1024 floats = 1024 float4; row stride = 256 float4.
        const float4* __restrict__ g =
            reinterpret_cast<const float4*>(x + (size_t)b * (4 * D));

        float nq = 0.f, na = 0.f, nc = 0.f, qa = 0.f, ac = 0.f, qc = 0.f;

        // Two stages of 12 front-batched LDG.128 (MLP=12), lane-coalesced.
        #pragma unroll
        for (int stage = 0; stage < 2; stage++) {
            float4 q4[4], a4[4], c4[4];
            const int j0 = stage * 4;
            #pragma unroll
            for (int j = 0; j < 4; j++) {
                const int idx = lid + 32 * (j0 + j);
                q4[j] = g[idx];          // row 4b+0
                a4[j] = g[256 + idx];    // row 4b+1
                c4[j] = g[768 + idx];    // row 4b+3
            }
            #pragma unroll
            for (int j = 0; j < 4; j++) {
                nq = fmaf(q4[j].x, q4[j].x, nq); nq = fmaf(q4[j].y, q4[j].y, nq);
                nq = fmaf(q4[j].z, q4[j].z, nq); nq = fmaf(q4[j].w, q4[j].w, nq);
                na = fmaf(a4[j].x, a4[j].x, na); na = fmaf(a4[j].y, a4[j].y, na);
                na = fmaf(a4[j].z, a4[j].z, na); na = fmaf(a4[j].w, a4[j].w, na);
                nc = fmaf(c4[j].x, c4[j].x, nc); nc = fmaf(c4[j].y, c4[j].y, nc);
                nc = fmaf(c4[j].z, c4[j].z, nc); nc = fmaf(c4[j].w, c4[j].w, nc);
                qa = fmaf(q4[j].x, a4[j].x, qa); qa = fmaf(q4[j].y, a4[j].y, qa);
                qa = fmaf(q4[j].z, a4[j].z, qa); qa = fmaf(q4[j].w, a4[j].w, qa);
                ac = fmaf(a4[j].x, c4[j].x, ac); ac = fmaf(a4[j].y, c4[j].y, ac);
                ac = fmaf(a4[j].z, c4[j].z, ac); ac = fmaf(a4[j].w, c4[j].w, ac);
                qc = fmaf(q4[j].x, c4[j].x, qc); qc = fmaf(q4[j].y, c4[j].y, qc);
                qc = fmaf(q4[j].z, c4[j].z, qc); qc = fmaf(q4[j].w, c4[j].w, qc);
            }
        }

        // Warp butterfly reduction on 6 quantities (no smem, no block sync)
        nq = warp_sum(nq); na = warp_sum(na); nc = warp_sum(nc);
        qa = warp_sum(qa); ac = warp_sum(ac); qc = warp_sum(qc);

        if (lid == 0) {
            float iq = 1.0f / fmaxf(sqrtf(nq), 1e-12f);
            float ia = 1.0f / fmaxf(sqrtf(na), 1e-12f);
            float ic = 1.0f / fmaxf(sqrtf(nc), 1e-12f);

            float dqa = qa * iq * ia;
            float dac = ac * ia * ic;
            float dqc = qc * iq * ic;

            float t0 = (float)target[b];
            float t1 = (float)target[NB + b];

            float eqa = __expf(dqa);
            float eac = __expf(dac);
            float eqc = __expf(dqc);

            float up   = fmaxf((1.0f - t0) * eqa + (1.0f - t1) * eqc, 1e-8f);
            float down = fmaxf(t0 * eqa + t1 * eqc, 1e-8f);

            locLoss += __logf(up + eac) - __logf(down);

            int correct = (dqa > dqc) ? 1 : 0;
            float eq = (correct == (int)t0) ? 1.0f : 0.0f;
            if (1 + b < out_size) out[1 + b] = eq;
        }
    }

    // Per-CTA aggregation: 8 warp-lane0 partials -> one atomic per CTA
    __shared__ float s[8];
    if (lid == 0) s[wid] = locLoss;
    __syncthreads();
    if (t == 0) {
        float sum = 0.f;
        #pragma unroll
        for (int w = 0; w < 8; w++) sum += s[w];
        atomicAdd(&out[0], sum * (1.0f / (float)NB));
    }
}

extern "C" void kernel_launch(void* const* d_in, const int* in_sizes, int n_in,
                              void* d_out, int out_size) {
    const float* x      = (const float*)d_in[0];
    const int*   target = (const int*)d_in[1];
    float*       out    = (float*)d_out;

    zero_out0_kernel<<<1, 32>>>(out);
    loss_kernel<<<GRID, THREADS>>>(x, target, out, out_size);
}